// round 16
// baseline (speedup 1.0000x reference)
#include <cuda_runtime.h>
#include <math.h>

// Problem constants
#define BB 32
#define SS 4096
#define HH 1024
#define NSPLIT 32                 // splits of S per batch -> 1024 blocks (~7/SM of work)
#define S_SPLIT (SS / NSPLIT)     // 128 rows per block
#define CHUNK 4                   // rows per chunk (small reg tile -> high occupancy)
#define NCHUNK (S_SPLIT / CHUNK)  // 32
#define TPB 256                   // threads; each owns 4 h-cols (float4)
#define F4_PER_B (HH / 4)         // 256

// Scratch for split-K partials (no runtime allocation allowed).
// energy = tanh(.) in [-1,1] => exp(energy) in [1/e, e]: no max-subtraction
// needed; softmax(e) == exp(e)/sum(exp(e)) exactly.
__device__ float g_cpart[BB * NSPLIT * HH];   // 4 MiB partial contexts
__device__ float g_l[BB * NSPLIT];            // partial normalizers
__device__ unsigned int g_ticket[BB];         // zero-init; last block resets

__global__ __launch_bounds__(TPB)
void attn_fused(const float* __restrict__ x, const float* __restrict__ w,
                float* __restrict__ out) {
    const int blk = blockIdx.x;
    const int b   = blk / NSPLIT;
    const int sp  = blk % NSPLIT;
    const int t   = threadIdx.x;
    const int wid = t >> 5;
    const int lane = t & 31;

    const float4* __restrict__ x4 =
        (const float4*)(x + ((size_t)b * SS + (size_t)sp * S_SPLIT) * HH);

    const float4 w4 = ((const float4*)w)[t];

    // Parity double-buffered smem: 2 barriers per chunk, no trailing WAR sync.
    __shared__ float sred[2][CHUNK * TPB];   // 8 KiB
    __shared__ float sp_sh[2][CHUNK];
    __shared__ unsigned int s_islast;

    float4 c = make_float4(0.f, 0.f, 0.f, 0.f);
    float l = 0.f;

    for (int ch = 0; ch < NCHUNK; ch++) {
        const int pb = ch & 1;
        const int row0 = ch * CHUNK;
        float4 xr[CHUNK];
        // Streaming loads (no reuse): evict-first; 4 independent LDG.128/thread.
        #pragma unroll
        for (int r = 0; r < CHUNK; r++) {
            xr[r] = __ldcs(&x4[(size_t)(row0 + r) * (HH / 4) + t]);
        }
        #pragma unroll
        for (int r = 0; r < CHUNK; r++) {
            sred[pb][r * TPB + t] = xr[r].x * w4.x + xr[r].y * w4.y
                                  + xr[r].z * w4.z + xr[r].w * w4.w;
        }
        __syncthreads();

        // warps 0..3 reduce rows 0..3; lane 0 -> p = exp(tanh(s)).
        if (wid < CHUNK) {
            const float* rowp = &sred[pb][wid * TPB];
            float s = rowp[lane] + rowp[lane + 32] + rowp[lane + 64] + rowp[lane + 96]
                    + rowp[lane + 128] + rowp[lane + 160] + rowp[lane + 192] + rowp[lane + 224];
            #pragma unroll
            for (int off = 16; off > 0; off >>= 1)
                s += __shfl_xor_sync(0xffffffffu, s, off);
            if (lane == 0) sp_sh[pb][wid] = expf(tanhf(s));
        }
        __syncthreads();

        #pragma unroll
        for (int r = 0; r < CHUNK; r++) {
            const float p = sp_sh[pb][r];
            l   += p;                      // redundant per-thread, identical value
            c.x += p * xr[r].x;
            c.y += p * xr[r].y;
            c.z += p * xr[r].z;
            c.w += p * xr[r].w;
        }
    }

    // Publish this split's partial.
    const int pidx = b * NSPLIT + sp;
    ((float4*)g_cpart)[(size_t)pidx * F4_PER_B + t] = c;
    if (t == 0) g_l[pidx] = l;

    // Release partials, then take a ticket for this batch.
    __threadfence();
    if (t == 0) {
        const unsigned int prev = atomicAdd(&g_ticket[b], 1u);
        s_islast = (prev == NSPLIT - 1) ? 1u : 0u;
    }
    __syncthreads();
    if (s_islast == 0) return;

    // ---- Last block of batch b: combine 32 L2-hot partials (fixed order) ----
    __threadfence();

    float L = 0.f;
    #pragma unroll
    for (int p = 0; p < NSPLIT; p++) L += g_l[b * NSPLIT + p];

    float4 acc = make_float4(0.f, 0.f, 0.f, 0.f);
    #pragma unroll
    for (int p = 0; p < NSPLIT; p++) {
        const float4 cp =
            ((const float4*)g_cpart)[(size_t)(b * NSPLIT + p) * F4_PER_B + t];
        acc.x += cp.x; acc.y += cp.y; acc.z += cp.z; acc.w += cp.w;
    }
    const float inv = 1.f / L;
    acc.x *= inv; acc.y *= inv; acc.z *= inv; acc.w *= inv;
    ((float4*)out)[(size_t)b * F4_PER_B + t] = acc;

    // Reset ticket for the next graph replay.
    if (t == 0) g_ticket[b] = 0u;
}

extern "C" void kernel_launch(void* const* d_in, const int* in_sizes, int n_in,
                              void* d_out, int out_size) {
    const float* x = (const float*)d_in[0];   // [B, S, H] fp32
    const float* w = (const float*)d_in[1];   // [H] fp32
    float* out = (float*)d_out;               // [B, H] fp32
    (void)in_sizes; (void)n_in; (void)out_size;

    attn_fused<<<BB * NSPLIT, TPB>>>(x, w, out);
}

// round 17
// speedup vs baseline: 1.2720x; 1.2720x over previous
#include <cuda_runtime.h>
#include <math.h>

// Problem constants
#define BB 32
#define SS 4096
#define HH 1024
#define NSPLIT 16                 // splits of S per batch (512 blocks) — best measured
#define S_SPLIT (SS / NSPLIT)     // 256 rows per block
#define CHUNK 8                   // rows held in registers per iteration
#define NCHUNK (S_SPLIT / CHUNK)  // 32
#define TPB 256                   // pass1 threads; each owns 4 h-cols (float4)
#define F4_PER_B (HH / 4)         // 256

// Scratch for split-K partials (no runtime allocation allowed).
// energy = tanh(.) in [-1,1] => exp(energy) in [1/e, e]: no max-subtraction
// needed; softmax(e) == exp(e)/sum(exp(e)) exactly.
__device__ float g_cpart[BB * NSPLIT * HH];   // 2 MiB partial contexts
__device__ float g_l[BB * NSPLIT];            // partial normalizers

__global__ __launch_bounds__(TPB)
void attn_pass1(const float* __restrict__ x, const float* __restrict__ w) {
    const int blk = blockIdx.x;
    const int b   = blk / NSPLIT;
    const int sp  = blk % NSPLIT;
    const int t   = threadIdx.x;
    const int wid = t >> 5;
    const int lane = t & 31;

    const float4* __restrict__ x4 =
        (const float4*)(x + ((size_t)b * SS + (size_t)sp * S_SPLIT) * HH);

    const float4 w4 = ((const float4*)w)[t];

    __shared__ float sred[CHUNK * TPB];   // partial dots, 8 KiB
    __shared__ float sp_sh[CHUNK];        // per-row numerators exp(tanh(.))

    float4 c = make_float4(0.f, 0.f, 0.f, 0.f);
    float l = 0.f;

    for (int ch = 0; ch < NCHUNK; ch++) {
        const int row0 = ch * CHUNK;
        float4 xr[CHUNK];
        // Streaming loads (no reuse): evict-first; 8 independent LDG.128/thread.
        #pragma unroll
        for (int r = 0; r < CHUNK; r++) {
            xr[r] = __ldcs(&x4[(size_t)(row0 + r) * (HH / 4) + t]);
        }
        #pragma unroll
        for (int r = 0; r < CHUNK; r++) {
            float pd = xr[r].x * w4.x + xr[r].y * w4.y
                     + xr[r].z * w4.z + xr[r].w * w4.w;
            sred[r * TPB + t] = pd;
        }
        __syncthreads();

        // warp `wid` reduces row `wid` (CHUNK == 8 == warps per block).
        // Lane reads its contiguous 8-float slice as 2x LDS.128 (conflict-free),
        // sums locally, then butterfly-reduces. lane 0 -> p = exp(tanh(s)).
        {
            const float4* rowq = (const float4*)&sred[wid * TPB];
            const float4 a = rowq[lane * 2];
            const float4 d = rowq[lane * 2 + 1];
            float s = ((a.x + a.y) + (a.z + a.w)) + ((d.x + d.y) + (d.z + d.w));
            #pragma unroll
            for (int off = 16; off > 0; off >>= 1)
                s += __shfl_xor_sync(0xffffffffu, s, off);
            if (lane == 0) sp_sh[wid] = expf(tanhf(s));
        }
        __syncthreads();

        #pragma unroll
        for (int r = 0; r < CHUNK; r++) {
            const float p = sp_sh[r];
            l   += p;                      // redundant per-thread, identical value
            c.x += p * xr[r].x;
            c.y += p * xr[r].y;
            c.z += p * xr[r].z;
            c.w += p * xr[r].w;
        }
        __syncthreads();   // protect sred/sp_sh before next chunk
    }

    const int pidx = b * NSPLIT + sp;
    ((float4*)g_cpart)[(size_t)pidx * F4_PER_B + t] = c;
    if (t == 0) g_l[pidx] = l;
}

// ---------------------------------------------------------------------------
// Pass 2: fixed-order sum of the 16 split partials per batch, / sum(l).
// grid = BB * HCHUNKS (256 blocks) x 256 threads. (R6 config — best measured.)
// ---------------------------------------------------------------------------
#define HCHUNKS 8
#define F4_PER_CHUNK (F4_PER_B / HCHUNKS)   // 32
#define SGRPS 8
#define SPLITS_PER_GRP (NSPLIT / SGRPS)     // 2

__global__ __launch_bounds__(256)
void attn_pass2(float* __restrict__ out) {
    const int b  = blockIdx.x / HCHUNKS;
    const int hc = blockIdx.x % HCHUNKS;
    const int t  = threadIdx.x;
    const int f4local = t & (F4_PER_CHUNK - 1);
    const int sgrp    = t >> 5;
    const int f4idx   = hc * F4_PER_CHUNK + f4local;

    // Normalizer: fixed-order sum of 16 broadcast loads.
    float L = 0.f;
    #pragma unroll
    for (int p = 0; p < NSPLIT; p++) L += g_l[b * NSPLIT + p];

    // Each thread sums its 2 splits (independent LDG.128s).
    float4 acc = make_float4(0.f, 0.f, 0.f, 0.f);
    #pragma unroll
    for (int i = 0; i < SPLITS_PER_GRP; i++) {
        const int p = sgrp * SPLITS_PER_GRP + i;
        const float4 cp =
            ((const float4*)g_cpart)[(size_t)(b * NSPLIT + p) * F4_PER_B + f4idx];
        acc.x += cp.x; acc.y += cp.y; acc.z += cp.z; acc.w += cp.w;
    }

    // Combine the 8 split-group partials per f4 slice (fixed order).
    __shared__ float4 sacc[SGRPS][F4_PER_CHUNK];
    sacc[sgrp][f4local] = acc;
    __syncthreads();

    if (sgrp == 0) {
        float4 r = sacc[0][f4local];
        #pragma unroll
        for (int g = 1; g < SGRPS; g++) {
            const float4 v = sacc[g][f4local];
            r.x += v.x; r.y += v.y; r.z += v.z; r.w += v.w;
        }
        const float inv = 1.f / L;
        r.x *= inv; r.y *= inv; r.z *= inv; r.w *= inv;
        ((float4*)out)[(size_t)b * F4_PER_B + f4idx] = r;
    }
}

extern "C" void kernel_launch(void* const* d_in, const int* in_sizes, int n_in,
                              void* d_out, int out_size) {
    const float* x = (const float*)d_in[0];   // [B, S, H] fp32
    const float* w = (const float*)d_in[1];   // [H] fp32
    float* out = (float*)d_out;               // [B, H] fp32
    (void)in_sizes; (void)n_in; (void)out_size;

    attn_pass1<<<BB * NSPLIT, TPB>>>(x, w);
    attn_pass2<<<BB * HCHUNKS, 256>>>(out);
}